// round 3
// baseline (speedup 1.0000x reference)
#include <cuda_runtime.h>

// RC timing on 200k independent 16-pin trees — all-register version.
// One thread per net. fa_local[i] in [0,i) => bottom-up subtree sums are exact
// with one descending sweep; top-down path sums with one ascending sweep.
// All dynamic parent indexing is done with fully unrolled predicated register
// selection (index range is [0,i), known at compile time per unrolled i), so
// there is ZERO shared memory and no local-memory spills from dynamic indexing.
//
// Output layout: out[(metric*3 + mode)*nPins + pin], metrics =
// {pin_cap, load, delay, ldelay, beta, impulse}, modes = {generic, rise, fall}.

#define NS  16
#define TPB 128

__global__ void __launch_bounds__(TPB, 4)
rct_kernel(const float* __restrict__ x, const float* __restrict__ y,
           const int* __restrict__ fa,
           const float* __restrict__ c0, const float* __restrict__ c1,
           const float* __restrict__ c2,
           float* __restrict__ out, int nNets, int nPins)
{
    const int t = blockIdx.x * TPB + threadIdx.x;
    if (t >= nNets) return;
    const int g = t * NS;

    // ---- local parent indices ---------------------------------------------
    int fl[NS];
    {
        const int4* fv = (const int4*)(fa + g);
        int4 a = fv[0], b = fv[1], c = fv[2], d = fv[3];
        int tmp[NS] = { a.x, a.y, a.z, a.w, b.x, b.y, b.z, b.w,
                        c.x, c.y, c.z, c.w, d.x, d.y, d.z, d.w };
#pragma unroll
        for (int i = 0; i < NS; i++) fl[i] = tmp[i] - g;
    }

    // ---- edge resistance == half edge cap: res = 0.1 * len / 2000 ---------
    float res[NS];
    res[0] = 0.0f;
    {
        const float4* xv = (const float4*)(x + g);
        const float4* yv = (const float4*)(y + g);
        float4 X0 = xv[0], X1 = xv[1], X2 = xv[2], X3 = xv[3];
        float4 Y0 = yv[0], Y1 = yv[1], Y2 = yv[2], Y3 = yv[3];
        float xr[NS] = { X0.x, X0.y, X0.z, X0.w, X1.x, X1.y, X1.z, X1.w,
                         X2.x, X2.y, X2.z, X2.w, X3.x, X3.y, X3.z, X3.w };
        float yr[NS] = { Y0.x, Y0.y, Y0.z, Y0.w, Y1.x, Y1.y, Y1.z, Y1.w,
                         Y2.x, Y2.y, Y2.z, Y2.w, Y3.x, Y3.y, Y3.z, Y3.w };
#pragma unroll
        for (int i = 1; i < NS; i++) {
            float xp = xr[0], yp = yr[0];
#pragma unroll
            for (int j = 1; j < i; j++)
                if (fl[i] == j) { xp = xr[j]; yp = yr[j]; }
            res[i] = (fabsf(xr[i] - xp) + fabsf(yr[i] - yp)) * 5.0e-5f;
        }
    }

    // ---- net wire caps: single-level scatter of half-edge caps ------------
    float nc[NS];
    nc[0] = 0.0f;
#pragma unroll
    for (int i = 1; i < NS; i++) nc[i] = res[i];
#pragma unroll
    for (int i = 1; i < NS; i++) {
        float v = res[i];
#pragma unroll
        for (int j = 0; j < i; j++)
            if (fl[i] == j) nc[j] += v;
    }

    // ---- per-mode timing (rolled loop: keeps SASS inside I$) --------------
#pragma unroll 1
    for (int m = 0; m < 3; m++) {
        const float* cb = (m == 0) ? c0 : ((m == 1) ? c1 : c2);

        float pc[NS];
        {
            const float4* cv = (const float4*)(cb + g);
            float4 A4 = cv[0], B4 = cv[1], C4 = cv[2], D4 = cv[3];
            float cr[NS] = { A4.x, A4.y, A4.z, A4.w, B4.x, B4.y, B4.z, B4.w,
                             C4.x, C4.y, C4.z, C4.w, D4.x, D4.y, D4.z, D4.w };
#pragma unroll
            for (int i = 0; i < NS; i++) pc[i] = cr[i] + nc[i];
        }
        float* po = out + (size_t)(0 * 3 + m) * nPins + g;
#pragma unroll
        for (int q = 0; q < 4; q++)
            ((float4*)po)[q] = make_float4(pc[4*q], pc[4*q+1], pc[4*q+2], pc[4*q+3]);

        // load: bottom-up subtree sum of pin_cap (in A)
        float A[NS];
#pragma unroll
        for (int i = 0; i < NS; i++) A[i] = pc[i];
#pragma unroll
        for (int i = NS - 1; i >= 1; i--) {
            float v = A[i];
#pragma unroll
            for (int j = 0; j < i; j++)
                if (fl[i] == j) A[j] += v;
        }
        po = out + (size_t)(1 * 3 + m) * nPins + g;
#pragma unroll
        for (int q = 0; q < 4; q++)
            ((float4*)po)[q] = make_float4(A[4*q], A[4*q+1], A[4*q+2], A[4*q+3]);

        // delay: top-down path sum, overwrites A (load -> delay) in place
        A[0] = 0.0f;
#pragma unroll
        for (int i = 1; i < NS; i++) {
            float pd = A[0];
#pragma unroll
            for (int j = 1; j < i; j++)
                if (fl[i] == j) pd = A[j];          // A[j<i] already = delay
            A[i] = fmaf(res[i], A[i], pd);          // A[i] still = load here
        }
        po = out + (size_t)(2 * 3 + m) * nPins + g;
#pragma unroll
        for (int q = 0; q < 4; q++)
            ((float4*)po)[q] = make_float4(A[4*q], A[4*q+1], A[4*q+2], A[4*q+3]);

        // ldelay: bottom-up subtree sum of pin_cap * delay (in B)
        float B[NS];
#pragma unroll
        for (int i = 0; i < NS; i++) B[i] = pc[i] * A[i];
#pragma unroll
        for (int i = NS - 1; i >= 1; i--) {
            float v = B[i];
#pragma unroll
            for (int j = 0; j < i; j++)
                if (fl[i] == j) B[j] += v;
        }
        po = out + (size_t)(3 * 3 + m) * nPins + g;
#pragma unroll
        for (int q = 0; q < 4; q++)
            ((float4*)po)[q] = make_float4(B[4*q], B[4*q+1], B[4*q+2], B[4*q+3]);

        // beta: top-down path sum, overwrites B (ldelay -> beta) in place
        B[0] = 0.0f;
#pragma unroll
        for (int i = 1; i < NS; i++) {
            float pb = B[0];
#pragma unroll
            for (int j = 1; j < i; j++)
                if (fl[i] == j) pb = B[j];
            B[i] = fmaf(res[i], B[i], pb);
        }
        po = out + (size_t)(4 * 3 + m) * nPins + g;
#pragma unroll
        for (int q = 0; q < 4; q++)
            ((float4*)po)[q] = make_float4(B[4*q], B[4*q+1], B[4*q+2], B[4*q+3]);

        // impulse = sqrt(max(2*beta - delay^2, 1e-12))
        float im[NS];
        im[0] = 1.0e-6f;
#pragma unroll
        for (int i = 1; i < NS; i++) {
            float q2 = fmaf(-A[i], A[i], B[i] + B[i]);
            q2 = fmaxf(q2, 1.0e-12f);
            im[i] = q2 * rsqrtf(q2);                // sqrt via MUFU.RSQ
        }
        po = out + (size_t)(5 * 3 + m) * nPins + g;
#pragma unroll
        for (int q = 0; q < 4; q++)
            ((float4*)po)[q] = make_float4(im[4*q], im[4*q+1], im[4*q+2], im[4*q+3]);
    }
}

extern "C" void kernel_launch(void* const* d_in, const int* in_sizes, int n_in,
                              void* d_out, int out_size)
{
    const float* x  = (const float*)d_in[0];
    const float* y  = (const float*)d_in[1];
    const int*   fa = (const int*)  d_in[4];
    const float* c0 = (const float*)d_in[8];
    const float* c1 = (const float*)d_in[9];
    const float* c2 = (const float*)d_in[10];

    const int nPins = in_sizes[0];
    const int nNets = in_sizes[3] - 1;   // net_flat_topo_sort_start has nNets+1

    const int grid = (nNets + TPB - 1) / TPB;
    rct_kernel<<<grid, TPB>>>(x, y, fa, c0, c1, c2, (float*)d_out, nNets, nPins);
}

// round 4
// speedup vs baseline: 3.7279x; 3.7279x over previous
#include <cuda_runtime.h>

// RC timing on 200k independent 16-pin trees.
// One thread per net; fa_local[i] in [0,i) => exact single-sweep bottom-up /
// top-down recurrences. Dynamic parent indexing via lane-transposed shared
// scratch ([slot][lane] => bank==lane, conflict-free, thread-private columns,
// zero syncs). KEY CHANGE vs R2: the three cap modes are interleaved inside
// every sweep iteration => 3 independent LDS->FADD->STS chains in flight,
// cutting the latency-bound critical path ~3x. All metric stores read back
// from shared (static offsets, pipelined) to keep register pressure low.
//
// Shared regions per warp (each 16 slots x 32 lanes):
//   W[m]  : pc -> load -> delay  (in place)
//   L[m]  : pc*delay -> ldelay -> beta (in place)
//   P[m]  : pin_cap (kept for ldelay base)
// Output: out[(metric*3 + mode)*nPins + pin].

#define NS     16
#define TPB    64
#define REGION 512          // 16 slots * 32 lanes
#define NREG   9

__global__ void __launch_bounds__(TPB, 6)
rct_kernel(const float* __restrict__ x, const float* __restrict__ y,
           const int* __restrict__ fa,
           const float* __restrict__ c0, const float* __restrict__ c1,
           const float* __restrict__ c2,
           float* __restrict__ out, int nNets, int nPins)
{
    __shared__ float sm[(TPB / 32) * NREG * REGION];   // 36864 B

    const int t = blockIdx.x * TPB + threadIdx.x;
    if (t >= nNets) return;

    float* sp = sm + (threadIdx.x >> 5) * (NREG * REGION) + (threadIdx.x & 31);
    float* Wp[3] = { sp + 0 * REGION, sp + 1 * REGION, sp + 2 * REGION };
    float* Lp[3] = { sp + 3 * REGION, sp + 4 * REGION, sp + 5 * REGION };
    float* Pp[3] = { sp + 6 * REGION, sp + 7 * REGION, sp + 8 * REGION };
    const float* cb[3] = { c0, c1, c2 };

    const int g = t * NS;

    // ---- local parent offsets (element offset into transposed scratch) ----
    int foff[NS];
    {
        const int4* fv = (const int4*)(fa + g);
        int4 a = fv[0], b = fv[1], c = fv[2], d = fv[3];
        int fl[NS] = { a.x, a.y, a.z, a.w, b.x, b.y, b.z, b.w,
                       c.x, c.y, c.z, c.w, d.x, d.y, d.z, d.w };
#pragma unroll
        for (int i = 0; i < NS; i++) foff[i] = (fl[i] - g) * 32;
    }

    // ---- edge resistance == half edge cap: 0.1 * len / 2000 ---------------
    float res[NS];
    res[0] = 0.0f;
    {
        const float4* xv = (const float4*)(x + g);
        const float4* yv = (const float4*)(y + g);
        float4 X0 = xv[0], X1 = xv[1], X2 = xv[2], X3 = xv[3];
        float4 Y0 = yv[0], Y1 = yv[1], Y2 = yv[2], Y3 = yv[3];
        float xr[NS] = { X0.x, X0.y, X0.z, X0.w, X1.x, X1.y, X1.z, X1.w,
                         X2.x, X2.y, X2.z, X2.w, X3.x, X3.y, X3.z, X3.w };
        float yr[NS] = { Y0.x, Y0.y, Y0.z, Y0.w, Y1.x, Y1.y, Y1.z, Y1.w,
                         Y2.x, Y2.y, Y2.z, Y2.w, Y3.x, Y3.y, Y3.z, Y3.w };
#pragma unroll
        for (int i = 1; i < NS; i++) {
            float xp = __ldg(x + g + (foff[i] >> 5));   // L1 hits (same lines)
            float yp = __ldg(y + g + (foff[i] >> 5));
            res[i] = (fabsf(xr[i] - xp) + fabsf(yr[i] - yp)) * 5.0e-5f;
        }
    }

    // ---- net wire caps: single-level scatter in W0 -------------------------
    float nc[NS];
    {
        Wp[0][0] = 0.0f;
#pragma unroll
        for (int i = 1; i < NS; i++) Wp[0][i * 32] = res[i];
#pragma unroll
        for (int i = NS - 1; i >= 1; i--) Wp[0][foff[i]] += res[i];
#pragma unroll
        for (int i = 0; i < NS; i++) nc[i] = Wp[0][i * 32];
    }

    // ---- pin caps (metric 0): build into P and W, store --------------------
#pragma unroll
    for (int m = 0; m < 3; m++) {
        const float4* cv = (const float4*)(cb[m] + g);
        float4 A = cv[0], B = cv[1], C = cv[2], D = cv[3];
        float cr[NS] = { A.x, A.y, A.z, A.w, B.x, B.y, B.z, B.w,
                         C.x, C.y, C.z, C.w, D.x, D.y, D.z, D.w };
        float pc[NS];
#pragma unroll
        for (int i = 0; i < NS; i++) {
            pc[i] = cr[i] + nc[i];
            Pp[m][i * 32] = pc[i];
            Wp[m][i * 32] = pc[i];
        }
        float* po = out + (size_t)(0 * 3 + m) * nPins + g;
#pragma unroll
        for (int q = 0; q < 4; q++)
            ((float4*)po)[q] = make_float4(pc[4*q], pc[4*q+1], pc[4*q+2], pc[4*q+3]);
    }

    // ---- LOAD: fused bottom-up sweep over W (3 chains interleaved) ---------
#pragma unroll
    for (int i = NS - 1; i >= 1; i--) {
#pragma unroll
        for (int m = 0; m < 3; m++) {
            float v = Wp[m][i * 32];
            Wp[m][foff[i]] += v;
        }
    }
#pragma unroll
    for (int m = 0; m < 3; m++) {           // readback + store metric 1
        float v[NS];
#pragma unroll
        for (int i = 0; i < NS; i++) v[i] = Wp[m][i * 32];
        float* po = out + (size_t)(1 * 3 + m) * nPins + g;
#pragma unroll
        for (int q = 0; q < 4; q++)
            ((float4*)po)[q] = make_float4(v[4*q], v[4*q+1], v[4*q+2], v[4*q+3]);
    }

    // ---- DELAY: fused top-down sweep, overwrites W in place ----------------
#pragma unroll
    for (int m = 0; m < 3; m++) Wp[m][0] = 0.0f;      // root delay
#pragma unroll
    for (int i = 1; i < NS; i++) {
#pragma unroll
        for (int m = 0; m < 3; m++) {
            float pd = Wp[m][foff[i]];        // parent already = delay
            float lv = Wp[m][i * 32];         // still = load
            Wp[m][i * 32] = fmaf(res[i], lv, pd);
        }
    }
#pragma unroll
    for (int m = 0; m < 3; m++) {           // readback + store metric 2
        float v[NS];
#pragma unroll
        for (int i = 0; i < NS; i++) v[i] = Wp[m][i * 32];
        float* po = out + (size_t)(2 * 3 + m) * nPins + g;
#pragma unroll
        for (int q = 0; q < 4; q++)
            ((float4*)po)[q] = make_float4(v[4*q], v[4*q+1], v[4*q+2], v[4*q+3]);
    }

    // ---- LDELAY: base pc*delay into L, fused bottom-up sweep ---------------
#pragma unroll
    for (int i = 0; i < NS; i++) {
#pragma unroll
        for (int m = 0; m < 3; m++)
            Lp[m][i * 32] = Pp[m][i * 32] * Wp[m][i * 32];
    }
#pragma unroll
    for (int i = NS - 1; i >= 1; i--) {
#pragma unroll
        for (int m = 0; m < 3; m++) {
            float v = Lp[m][i * 32];
            Lp[m][foff[i]] += v;
        }
    }
#pragma unroll
    for (int m = 0; m < 3; m++) {           // readback + store metric 3
        float v[NS];
#pragma unroll
        for (int i = 0; i < NS; i++) v[i] = Lp[m][i * 32];
        float* po = out + (size_t)(3 * 3 + m) * nPins + g;
#pragma unroll
        for (int q = 0; q < 4; q++)
            ((float4*)po)[q] = make_float4(v[4*q], v[4*q+1], v[4*q+2], v[4*q+3]);
    }

    // ---- BETA: fused top-down sweep over L; impulse from W (delay) ---------
    float be[3][NS];
#pragma unroll
    for (int m = 0; m < 3; m++) { be[m][0] = 0.0f; Lp[m][0] = 0.0f; }
#pragma unroll
    for (int i = 1; i < NS; i++) {
#pragma unroll
        for (int m = 0; m < 3; m++) {
            float pb = Lp[m][foff[i]];        // parent already = beta
            float lv = Lp[m][i * 32];         // still = ldelay
            float b  = fmaf(res[i], lv, pb);
            be[m][i] = b;
            Lp[m][i * 32] = b;
        }
    }
#pragma unroll
    for (int m = 0; m < 3; m++) {           // store metric 4 + compute/store 5
        float* po4 = out + (size_t)(4 * 3 + m) * nPins + g;
#pragma unroll
        for (int q = 0; q < 4; q++)
            ((float4*)po4)[q] = make_float4(be[m][4*q], be[m][4*q+1],
                                            be[m][4*q+2], be[m][4*q+3]);
        float im[NS];
        im[0] = 1.0e-6f;
#pragma unroll
        for (int i = 1; i < NS; i++) {
            float dlv = Wp[m][i * 32];        // W still holds delay
            float q2 = fmaf(-dlv, dlv, be[m][i] + be[m][i]);
            q2 = fmaxf(q2, 1.0e-12f);
            im[i] = q2 * rsqrtf(q2);          // sqrt via MUFU.RSQ
        }
        float* po5 = out + (size_t)(5 * 3 + m) * nPins + g;
#pragma unroll
        for (int q = 0; q < 4; q++)
            ((float4*)po5)[q] = make_float4(im[4*q], im[4*q+1], im[4*q+2], im[4*q+3]);
    }
}

extern "C" void kernel_launch(void* const* d_in, const int* in_sizes, int n_in,
                              void* d_out, int out_size)
{
    const float* x  = (const float*)d_in[0];
    const float* y  = (const float*)d_in[1];
    const int*   fa = (const int*)  d_in[4];
    const float* c0 = (const float*)d_in[8];
    const float* c1 = (const float*)d_in[9];
    const float* c2 = (const float*)d_in[10];

    const int nPins = in_sizes[0];
    const int nNets = in_sizes[3] - 1;   // net_flat_topo_sort_start has nNets+1

    const int grid = (nNets + TPB - 1) / TPB;
    rct_kernel<<<grid, TPB>>>(x, y, fa, c0, c1, c2, (float*)d_out, nNets, nPins);
}

// round 5
// speedup vs baseline: 4.4396x; 1.1909x over previous
#include <cuda_runtime.h>

// RC timing on 200k independent 16-pin trees — mode-per-thread version.
// 3 threads per net: each thread computes ONE cap mode end-to-end, so the
// serial sweep chain per thread is 1/3 of the all-modes-per-thread version
// and register pressure stays low (higher occupancy).
//
// Warp layout: each warp = 32 nets x 1 mode. Block = 192 threads = 6 warps
// = 2 net-groups x 3 modes. Warps are fully independent (no syncs).
//
// fa_local[i] in [0,i) => bottom-up subtree sums exact in one descending
// sweep, top-down path sums in one ascending sweep. Dynamic parent indexing
// via lane-transposed shared scratch ([slot][lane] => bank==lane,
// conflict-free, thread-private columns).
//
// Per-warp shared regions (16 slots x 32 lanes each):
//   W : x -> pc -> load -> delay      (in place)
//   L : y -> ldelay -> beta           (in place)
// Output: out[(metric*3 + mode)*nPins + pin].

#define NS       16
#define TPB      192
#define REGION   512            // 16 * 32 floats
#define NETS_PB  64             // 2 net-groups of 32

#define LD16(dst, src)                                                        \
    {                                                                         \
        const float4* _v = (const float4*)(src);                              \
        float4 _a = _v[0], _b = _v[1], _c = _v[2], _d = _v[3];                \
        dst[0]=_a.x; dst[1]=_a.y; dst[2]=_a.z; dst[3]=_a.w;                   \
        dst[4]=_b.x; dst[5]=_b.y; dst[6]=_b.z; dst[7]=_b.w;                   \
        dst[8]=_c.x; dst[9]=_c.y; dst[10]=_c.z; dst[11]=_c.w;                 \
        dst[12]=_d.x; dst[13]=_d.y; dst[14]=_d.z; dst[15]=_d.w;               \
    }

#define ST16(metric, arr)                                                     \
    {                                                                         \
        float* _po = out + (size_t)((metric) * 3 + mode) * nPins + g;         \
        _Pragma("unroll")                                                     \
        for (int _q = 0; _q < 4; _q++)                                        \
            ((float4*)_po)[_q] = make_float4(arr[4*_q], arr[4*_q+1],          \
                                             arr[4*_q+2], arr[4*_q+3]);       \
    }

__global__ void __launch_bounds__(TPB, 4)
rct_kernel(const float* __restrict__ x, const float* __restrict__ y,
           const int* __restrict__ fa,
           const float* __restrict__ c0, const float* __restrict__ c1,
           const float* __restrict__ c2,
           float* __restrict__ out, int nNets, int nPins)
{
    __shared__ float sm[(TPB / 32) * 2 * REGION];    // 24 KB

    const int wib  = threadIdx.x >> 5;     // 0..5
    const int lane = threadIdx.x & 31;
    const int mode = wib % 3;
    const int grp  = wib / 3;              // 0..1
    const int t    = blockIdx.x * NETS_PB + grp * 32 + lane;   // net id
    if (t >= nNets) return;
    const int g = t * NS;

    float* W = sm + wib * (2 * REGION) + lane;            // region 0
    float* L = W + REGION;                                // region 1
    const float* cb = (mode == 0) ? c0 : ((mode == 1) ? c1 : c2);

    // ---- parent offsets ---------------------------------------------------
    int foff[NS];
    {
        const int4* fv = (const int4*)(fa + g);
        int4 a = fv[0], b = fv[1], c = fv[2], d = fv[3];
        int fl[NS] = { a.x, a.y, a.z, a.w, b.x, b.y, b.z, b.w,
                       c.x, c.y, c.z, c.w, d.x, d.y, d.z, d.w };
#pragma unroll
        for (int i = 0; i < NS; i++) foff[i] = (fl[i] - g) * 32;
    }

    // ---- edge res (== half edge cap): parent coords via shared ------------
    float res[NS];
    res[0] = 0.0f;
    {
        float xr[NS], yr[NS];
        LD16(xr, x + g);
        LD16(yr, y + g);
#pragma unroll
        for (int i = 0; i < NS; i++) { W[i * 32] = xr[i]; L[i * 32] = yr[i]; }
#pragma unroll
        for (int i = 1; i < NS; i++) {
            float xp = W[foff[i]];
            float yp = L[foff[i]];
            res[i] = (fabsf(xr[i] - xp) + fabsf(yr[i] - yp)) * 5.0e-5f;
        }
    }

    // ---- pin caps: W[i] = base + own half-cap, scatter half-caps up -------
    float u[NS];                                 // pc, later ldelay/beta
    {
        float cr[NS];
        LD16(cr, cb + g);
        W[0] = cr[0];
#pragma unroll
        for (int i = 1; i < NS; i++) W[i * 32] = cr[i] + res[i];
#pragma unroll
        for (int i = NS - 1; i >= 1; i--) W[foff[i]] += res[i];
#pragma unroll
        for (int i = 0; i < NS; i++) u[i] = W[i * 32];   // u = pin_cap
    }
    ST16(0, u);

    // ---- load: bottom-up subtree sum of pin_cap (in place in W) -----------
    float v[NS];                                 // load, then delay
#pragma unroll
    for (int i = NS - 1; i >= 1; i--) {
        v[i] = W[i * 32];                        // final (descendants done)
        W[foff[i]] += v[i];
    }
    v[0] = W[0];
    ST16(1, v);

    // ---- delay: top-down path sum (in place in W); v: load -> delay -------
    W[0] = 0.0f;
    v[0] = 0.0f;
#pragma unroll
    for (int i = 1; i < NS; i++) {
        float pd = W[foff[i]];                   // parent already = delay
        float d  = fmaf(res[i], v[i], pd);
        W[i * 32] = d;
        v[i] = d;
    }
    ST16(2, v);

    // ---- ldelay: base = pc*delay into L, bottom-up sum --------------------
#pragma unroll
    for (int i = 0; i < NS; i++) L[i * 32] = u[i] * v[i];
#pragma unroll
    for (int i = NS - 1; i >= 1; i--) {
        u[i] = L[i * 32];                        // u: pc -> ldelay
        L[foff[i]] += u[i];
    }
    u[0] = L[0];
    ST16(3, u);

    // ---- beta: top-down path sum (in place in L); u: ldelay -> beta -------
    L[0] = 0.0f;
    u[0] = 0.0f;
#pragma unroll
    for (int i = 1; i < NS; i++) {
        float pb = L[foff[i]];
        float b  = fmaf(res[i], u[i], pb);
        L[i * 32] = b;
        u[i] = b;
    }
    ST16(4, u);

    // ---- impulse = sqrt(max(2*beta - delay^2, 1e-12)) ---------------------
    float im[NS];
    im[0] = 1.0e-6f;
#pragma unroll
    for (int i = 1; i < NS; i++) {
        float q2 = fmaf(-v[i], v[i], u[i] + u[i]);
        q2 = fmaxf(q2, 1.0e-12f);
        im[i] = q2 * rsqrtf(q2);                 // sqrt via MUFU.RSQ
    }
    ST16(5, im);
}

extern "C" void kernel_launch(void* const* d_in, const int* in_sizes, int n_in,
                              void* d_out, int out_size)
{
    const float* x  = (const float*)d_in[0];
    const float* y  = (const float*)d_in[1];
    const int*   fa = (const int*)  d_in[4];
    const float* c0 = (const float*)d_in[8];
    const float* c1 = (const float*)d_in[9];
    const float* c2 = (const float*)d_in[10];

    const int nPins = in_sizes[0];
    const int nNets = in_sizes[3] - 1;   // net_flat_topo_sort_start has nNets+1

    const int grid = (nNets + NETS_PB - 1) / NETS_PB;
    rct_kernel<<<grid, TPB>>>(x, y, fa, c0, c1, c2, (float*)d_out, nNets, nPins);
}

// round 8
// speedup vs baseline: 4.6446x; 1.0462x over previous
#include <cuda_runtime.h>

// RC timing on 200k independent 16-pin trees — mode-per-thread with
// block-level geometry dedup.
//
// Block = 192 threads = 6 warps = 2 net-groups x 3 modes; warp (grp,mode)
// handles 32 nets, lane = net. fa_local[i] in [0,i) => bottom-up subtree
// sums exact in one descending sweep, top-down path sums in one ascending
// sweep. Dynamic parent indexing via lane-transposed shared scratch
// ([slot][lane] => bank == lane, conflict-free, thread-private columns).
//
// Mode-0 warps compute the mode-independent geometry (edge res, wire caps nc,
// parent offsets) ONCE per net and publish via shared; modes 1/2 read it
// back after one __syncthreads. (res,nc) published interleaved as float2.
// Slot 15 is never a parent (fa_local < 15) so its shared seed/writeback is
// elided in every sweep.
//
// Output: out[(metric*3 + mode)*nPins + pin].

#define NS       16
#define TPB      192
#define NETS_PB  64

#define LD16(dst, src)                                                        \
    {                                                                         \
        const float4* _v = (const float4*)(src);                              \
        float4 _a = _v[0], _b = _v[1], _c = _v[2], _d = _v[3];                \
        dst[0]=_a.x; dst[1]=_a.y; dst[2]=_a.z; dst[3]=_a.w;                   \
        dst[4]=_b.x; dst[5]=_b.y; dst[6]=_b.z; dst[7]=_b.w;                   \
        dst[8]=_c.x; dst[9]=_c.y; dst[10]=_c.z; dst[11]=_c.w;                 \
        dst[12]=_d.x; dst[13]=_d.y; dst[14]=_d.z; dst[15]=_d.w;               \
    }

#define ST16(metric, arr)                                                     \
    {                                                                         \
        float* _po = out + (size_t)((metric) * 3 + mode) * nPins + g;         \
        _Pragma("unroll")                                                     \
        for (int _q = 0; _q < 4; _q++)                                        \
            ((float4*)_po)[_q] = make_float4(arr[4*_q], arr[4*_q+1],          \
                                             arr[4*_q+2], arr[4*_q+3]);       \
    }

__global__ void __launch_bounds__(TPB, 4)
rct_kernel(const float* __restrict__ x, const float* __restrict__ y,
           const int* __restrict__ fa,
           const float* __restrict__ c0, const float* __restrict__ c1,
           const float* __restrict__ c2,
           float* __restrict__ out, int nNets, int nPins)
{
    __shared__ float Wsm[6 * 512];       // per-warp sweep scratch, 12 KB
    __shared__ float RNsm[2 * 1024];     // per-group (x,y)->(res,nc) fl2, 8 KB
    __shared__ int   Fsm[2 * 512];       // per-group parent offsets, 4 KB

    const int wib  = threadIdx.x >> 5;   // 0..5
    const int lane = threadIdx.x & 31;
    const int mode = wib % 3;
    const int grp  = wib / 3;            // 0..1
    const int t    = blockIdx.x * NETS_PB + grp * 32 + lane;   // net id
    const bool act = (t < nNets);
    const int g    = t * NS;

    float* W  = Wsm  + wib * 512 + lane;        // [slot][lane] column
    float* RN = RNsm + grp * 1024 + lane * 2;   // float2 column
    int*   F  = Fsm  + grp * 512 + lane;

    int   foff[NS];
    float res[NS];
    float nc[NS];

    // ---- geometry (mode-0 warps only): res, nc, foff once per net ---------
    if (act && mode == 0) {
        {
            const int4* fv = (const int4*)(fa + g);
            int4 a = fv[0], b = fv[1], c = fv[2], d = fv[3];
            int fl[NS] = { a.x, a.y, a.z, a.w, b.x, b.y, b.z, b.w,
                           c.x, c.y, c.z, c.w, d.x, d.y, d.z, d.w };
#pragma unroll
            for (int i = 0; i < NS; i++) {
                foff[i] = (fl[i] - g) * 32;
                F[i * 32] = foff[i];
            }
        }
        float xr[NS], yr[NS];
        LD16(xr, x + g);
        LD16(yr, y + g);
#pragma unroll
        for (int i = 0; i < NS; i++)
            *(float2*)(RN + i * 64) = make_float2(xr[i], yr[i]);
        res[0] = 0.0f;
#pragma unroll
        for (int i = 1; i < NS; i++) {
            float2 p = *(const float2*)(RN + foff[i] * 2);
            res[i] = (fabsf(xr[i] - p.x) + fabsf(yr[i] - p.y)) * 5.0e-5f;
        }
        // wire caps: scatter half-edge caps up one level (in own W region)
        W[0] = 0.0f;
#pragma unroll
        for (int i = 1; i < NS; i++) W[i * 32] = res[i];
#pragma unroll
        for (int i = NS - 1; i >= 1; i--) W[foff[i]] += res[i];
#pragma unroll
        for (int i = 0; i < NS; i++) nc[i] = W[i * 32];
        // publish (overwrites xy staging — all reads done)
#pragma unroll
        for (int i = 0; i < NS; i++)
            *(float2*)(RN + i * 64) = make_float2(res[i], nc[i]);
    }

    __syncthreads();
    if (!act) return;

    if (mode != 0) {
#pragma unroll
        for (int i = 0; i < NS; i++) foff[i] = F[i * 32];
#pragma unroll
        for (int i = 0; i < NS; i++) {
            float2 rn = *(const float2*)(RN + i * 64);
            res[i] = rn.x; nc[i] = rn.y;
        }
    }

    const float* cb = (mode == 0) ? c0 : ((mode == 1) ? c1 : c2);

    // ---- pin caps (metric 0) ----------------------------------------------
    float u[NS], v[NS];          // u: pc -> ldelay -> beta ; v: load -> delay
    {
        float cr[NS];
        LD16(cr, cb + g);
#pragma unroll
        for (int i = 0; i < NS; i++) u[i] = cr[i] + nc[i];
    }
    ST16(0, u);

    // ---- load: bottom-up subtree sum of pin_cap ---------------------------
#pragma unroll
    for (int i = 0; i < NS - 1; i++) W[i * 32] = u[i];   // slot 15 stays in reg
    v[NS - 1] = u[NS - 1];
    W[foff[NS - 1]] += v[NS - 1];
#pragma unroll
    for (int i = NS - 2; i >= 1; i--) {
        v[i] = W[i * 32];                                // descendants done
        W[foff[i]] += v[i];
    }
    v[0] = W[0];
    ST16(1, v);

    // ---- delay: top-down path sum; v: load -> delay -----------------------
    W[0] = 0.0f;
    v[0] = 0.0f;                                         // root delay = 0 (R6 bug)
#pragma unroll
    for (int i = 1; i < NS; i++) {
        float pd = W[foff[i]];                           // parent = delay
        float d  = fmaf(res[i], v[i], pd);
        if (i < NS - 1) W[i * 32] = d;                   // 15 never a parent
        v[i] = d;
    }
    ST16(2, v);

    // ---- ldelay: bottom-up subtree sum of pc*delay; u: pc -> ldelay -------
#pragma unroll
    for (int i = 0; i < NS - 1; i++) W[i * 32] = u[i] * v[i];
    u[NS - 1] = u[NS - 1] * v[NS - 1];
    W[foff[NS - 1]] += u[NS - 1];
#pragma unroll
    for (int i = NS - 2; i >= 1; i--) {
        u[i] = W[i * 32];
        W[foff[i]] += u[i];
    }
    u[0] = W[0];
    ST16(3, u);

    // ---- beta: top-down path sum; u: ldelay -> beta -----------------------
    W[0] = 0.0f;
    u[0] = 0.0f;                                         // root beta = 0 (R6 bug)
#pragma unroll
    for (int i = 1; i < NS; i++) {
        float pb = W[foff[i]];
        float b  = fmaf(res[i], u[i], pb);
        if (i < NS - 1) W[i * 32] = b;
        u[i] = b;
    }
    ST16(4, u);

    // ---- impulse = sqrt(max(2*beta - delay^2, 1e-12)) ---------------------
    {
        float* po = out + (size_t)(5 * 3 + mode) * nPins + g;
#pragma unroll
        for (int q = 0; q < 4; q++) {
            float o[4];
#pragma unroll
            for (int k = 0; k < 4; k++) {
                int i = 4 * q + k;
                if (i == 0) { o[k] = 1.0e-6f; continue; }
                float q2 = fmaf(-v[i], v[i], u[i] + u[i]);
                q2 = fmaxf(q2, 1.0e-12f);
                o[k] = q2 * rsqrtf(q2);                  // sqrt via MUFU.RSQ
            }
            ((float4*)po)[q] = make_float4(o[0], o[1], o[2], o[3]);
        }
    }
}

extern "C" void kernel_launch(void* const* d_in, const int* in_sizes, int n_in,
                              void* d_out, int out_size)
{
    const float* x  = (const float*)d_in[0];
    const float* y  = (const float*)d_in[1];
    const int*   fa = (const int*)  d_in[4];
    const float* c0 = (const float*)d_in[8];
    const float* c1 = (const float*)d_in[9];
    const float* c2 = (const float*)d_in[10];

    const int nPins = in_sizes[0];
    const int nNets = in_sizes[3] - 1;   // net_flat_topo_sort_start has nNets+1

    const int grid = (nNets + NETS_PB - 1) / NETS_PB;
    rct_kernel<<<grid, TPB>>>(x, y, fa, c0, c1, c2, (float*)d_out, nNets, nPins);
}